// round 2
// baseline (speedup 1.0000x reference)
#include <cuda_runtime.h>
#include <math.h>

#define NN 50000
#define EE 800000

// ---------------- scratch (static device globals; no allocation) ----------------
__device__ float g_hA[(size_t)NN * 512];
__device__ float g_hB[(size_t)NN * 512];
__device__ float g_agg[(size_t)NN * 256];
__device__ int   g_deg[NN];
__device__ float g_deginv[NN];
__device__ int   g_rowptr[NN + 1];
__device__ int   g_cursor[NN];
__device__ int   g_col[EE];
__device__ int   g_aux[64];

// ---------------- CSR build ----------------
__global__ void k_zero_deg() {
    int i = blockIdx.x * blockDim.x + threadIdx.x;
    if (i < NN) g_deg[i] = 0;
}

__global__ void k_hist(const int* __restrict__ dst) {
    int e = blockIdx.x * blockDim.x + threadIdx.x;
    if (e < EE) atomicAdd(&g_deg[dst[e]], 1);
}

// block-level inclusive scan of deg -> rowptr[i+1], block totals -> aux
__global__ void k_scanA() {
    __shared__ int s[1024];
    int t = threadIdx.x;
    int i = blockIdx.x * 1024 + t;
    int v = (i < NN) ? g_deg[i] : 0;
    s[t] = v;
    __syncthreads();
    for (int off = 1; off < 1024; off <<= 1) {
        int x = (t >= off) ? s[t - off] : 0;
        __syncthreads();
        s[t] += x;
        __syncthreads();
    }
    if (i < NN) g_rowptr[i + 1] = s[t];
    if (t == 1023) g_aux[blockIdx.x] = s[t];
    if (i == 0) g_rowptr[0] = 0;
}

__global__ void k_scanB(int nb) {
    if (threadIdx.x == 0 && blockIdx.x == 0) {
        int run = 0;
        for (int b = 0; b < nb; b++) {
            int v = g_aux[b];
            g_aux[b] = run;
            run += v;
        }
    }
}

__global__ void k_scanC() {
    int t = threadIdx.x;
    int i = blockIdx.x * 1024 + t;
    if (i < NN) g_rowptr[i + 1] += g_aux[blockIdx.x];
}

__global__ void k_prep() {
    int i = blockIdx.x * blockDim.x + threadIdx.x;
    if (i < NN) {
        g_cursor[i] = g_rowptr[i];
        float d = (float)g_deg[i];
        g_deginv[i] = 1.0f / fmaxf(d, 1.0f);
    }
}

__global__ void k_scatter(const int* __restrict__ src, const int* __restrict__ dst) {
    int e = blockIdx.x * blockDim.x + threadIdx.x;
    if (e < EE) {
        int d = dst[e];
        int pos = atomicAdd(&g_cursor[d], 1);
        g_col[pos] = src[e];
    }
}

// ---------------- mean aggregation: warp per node, 2-way neighbor unroll ----------------
template <int DIN>
__global__ void k_agg(const float* __restrict__ h, float* __restrict__ agg) {
    int warp = (blockIdx.x * blockDim.x + threadIdx.x) >> 5;
    int lane = threadIdx.x & 31;
    if (warp >= NN) return;
    constexpr int C = DIN / 32;
    float acc[C];
#pragma unroll
    for (int c = 0; c < C; c++) acc[c] = 0.0f;
    const int s = g_rowptr[warp];
    const int e = g_rowptr[warp + 1];
    int j = s;
    for (; j + 1 < e; j += 2) {
        int s0 = g_col[j];
        int s1 = g_col[j + 1];
        const float* r0 = h + (size_t)s0 * DIN;
        const float* r1 = h + (size_t)s1 * DIN;
        float v0[C], v1[C];
#pragma unroll
        for (int c = 0; c < C; c++) v0[c] = r0[lane + 32 * c];
#pragma unroll
        for (int c = 0; c < C; c++) v1[c] = r1[lane + 32 * c];
#pragma unroll
        for (int c = 0; c < C; c++) acc[c] += v0[c] + v1[c];
    }
    if (j < e) {
        const float* r0 = h + (size_t)g_col[j] * DIN;
#pragma unroll
        for (int c = 0; c < C; c++) acc[c] += r0[lane + 32 * c];
    }
    float di = g_deginv[warp];
    float* out = agg + (size_t)warp * DIN;
#pragma unroll
    for (int c = 0; c < C; c++) out[lane + 32 * c] = acc[c] * di;
}

// ---------------- fused dual GEMM + bias + relu ----------------
// C[m][n] = relu( sum_k A1[m][k]*W1[n][k] + sum_k A2[m][k]*W2[n][k] + bias[n] )
// A row-major [M,K], W row-major [NO,K]. K % 16 == 0, NO % BN == 0.
template <int BM, int BN, int TM, int TN>
__global__ void k_gemm2(const float* __restrict__ A1, const float* __restrict__ A2,
                        const float* __restrict__ W1, const float* __restrict__ W2,
                        const float* __restrict__ bias, float* __restrict__ C,
                        int M, int K, int NO) {
    constexpr int BK = 16;
    constexpr int THREADS = (BM / TM) * (BN / TN);  // 256
    __shared__ float sA[BK][BM + 4];
    __shared__ float sB[BK][BN + 4];

    const int tid = threadIdx.x;
    const int ntx = BN / TN;
    const int tx = tid % ntx;
    const int ty = tid / ntx;
    const int row0 = blockIdx.x * BM + ty * TM;
    const int col0 = blockIdx.y * BN + tx * TN;

    float acc[TM][TN];
#pragma unroll
    for (int i = 0; i < TM; i++)
#pragma unroll
        for (int j = 0; j < TN; j++) acc[i][j] = 0.0f;

    for (int op = 0; op < 2; op++) {
        const float* A = op ? A2 : A1;
        const float* W = op ? W2 : W1;
        for (int k0 = 0; k0 < K; k0 += BK) {
            // load A tile (BM x BK) as float4, store transposed
            constexpr int A_F4 = BM * BK / 4;
#pragma unroll
            for (int f = tid; f < A_F4; f += THREADS) {
                int r = f / (BK / 4);
                int c4 = f % (BK / 4);
                int gr = blockIdx.x * BM + r;
                float4 v = make_float4(0.f, 0.f, 0.f, 0.f);
                if (gr < M)
                    v = *reinterpret_cast<const float4*>(&A[(size_t)gr * K + k0 + c4 * 4]);
                sA[c4 * 4 + 0][r] = v.x;
                sA[c4 * 4 + 1][r] = v.y;
                sA[c4 * 4 + 2][r] = v.z;
                sA[c4 * 4 + 3][r] = v.w;
            }
            // load W tile (BN x BK) as float4, store transposed
            constexpr int B_F4 = BN * BK / 4;
#pragma unroll
            for (int f = tid; f < B_F4; f += THREADS) {
                int r = f / (BK / 4);
                int c4 = f % (BK / 4);
                int gn = blockIdx.y * BN + r;
                float4 v = *reinterpret_cast<const float4*>(&W[(size_t)gn * K + k0 + c4 * 4]);
                sB[c4 * 4 + 0][r] = v.x;
                sB[c4 * 4 + 1][r] = v.y;
                sB[c4 * 4 + 2][r] = v.z;
                sB[c4 * 4 + 3][r] = v.w;
            }
            __syncthreads();
#pragma unroll
            for (int kk = 0; kk < BK; kk++) {
                float a[TM], b[TN];
#pragma unroll
                for (int i = 0; i < TM; i++) a[i] = sA[kk][ty * TM + i];
#pragma unroll
                for (int j = 0; j < TN; j++) b[j] = sB[kk][tx * TN + j];
#pragma unroll
                for (int i = 0; i < TM; i++)
#pragma unroll
                    for (int j = 0; j < TN; j++) acc[i][j] += a[i] * b[j];
            }
            __syncthreads();
        }
    }
#pragma unroll
    for (int i = 0; i < TM; i++) {
        int gr = row0 + i;
        if (gr < M) {
#pragma unroll
            for (int j = 0; j < TN; j++) {
                float v = acc[i][j] + bias[col0 + j];
                v = fmaxf(v, 0.0f);
                C[(size_t)gr * NO + col0 + j] = v;
            }
        }
    }
}

// ---------------- final linear (512 -> 4) + softmax, warp per node ----------------
__global__ void k_out(const float* __restrict__ h, const float* __restrict__ Wout,
                      const float* __restrict__ bout, float* __restrict__ out) {
    int warp = (blockIdx.x * blockDim.x + threadIdx.x) >> 5;
    int lane = threadIdx.x & 31;
    if (warp >= NN) return;
    const float* row = h + (size_t)warp * 512;
    float acc[4] = {0.f, 0.f, 0.f, 0.f};
    for (int j = lane; j < 512; j += 32) {
        float x = row[j];
#pragma unroll
        for (int o = 0; o < 4; o++) acc[o] += x * Wout[o * 512 + j];
    }
#pragma unroll
    for (int o = 0; o < 4; o++) {
#pragma unroll
        for (int off = 16; off; off >>= 1) acc[o] += __shfl_xor_sync(0xffffffffu, acc[o], off);
    }
    if (lane == 0) {
        float l[4];
#pragma unroll
        for (int o = 0; o < 4; o++) l[o] = acc[o] + bout[o];
        float m = fmaxf(fmaxf(l[0], l[1]), fmaxf(l[2], l[3]));
        float e[4], s = 0.f;
#pragma unroll
        for (int o = 0; o < 4; o++) {
            e[o] = expf(l[o] - m);
            s += e[o];
        }
        float inv = 1.0f / s;
#pragma unroll
        for (int o = 0; o < 4; o++) out[(size_t)warp * 4 + o] = e[o] * inv;
    }
}

// ---------------- host side ----------------
extern "C" void kernel_launch(void* const* d_in, const int* in_sizes, int n_in,
                              void* d_out, int out_size) {
    const float* x = (const float*)d_in[0];
    const float* Wl[5];
    const float* bl[5];
    const float* Wr[5];
    for (int i = 0; i < 5; i++) {
        Wl[i] = (const float*)d_in[1 + 3 * i];
        bl[i] = (const float*)d_in[2 + 3 * i];
        Wr[i] = (const float*)d_in[3 + 3 * i];
    }
    const float* Wout = (const float*)d_in[16];
    const float* bout = (const float*)d_in[17];
    const int* edge = (const int*)d_in[18];
    const int* srcp = edge;        // edge_index[0]
    const int* dstp = edge + EE;   // edge_index[1]
    float* out = (float*)d_out;

    float *hA, *hB, *agg;
    cudaGetSymbolAddress((void**)&hA, g_hA);
    cudaGetSymbolAddress((void**)&hB, g_hB);
    cudaGetSymbolAddress((void**)&agg, g_agg);

    const int nbScan = (NN + 1023) / 1024;  // 49

    // ---- CSR build ----
    k_zero_deg<<<(NN + 255) / 256, 256>>>();
    k_hist<<<(EE + 255) / 256, 256>>>(dstp);
    k_scanA<<<nbScan, 1024>>>();
    k_scanB<<<1, 32>>>(nbScan);
    k_scanC<<<nbScan, 1024>>>();
    k_prep<<<(NN + 255) / 256, 256>>>();
    k_scatter<<<(EE + 255) / 256, 256>>>(srcp, dstp);

    const int aggBlocks = (NN * 32 + 255) / 256;

    // layer 0: 128 -> 128   (in: x, out: hA)
    k_agg<128><<<aggBlocks, 256>>>(x, agg);
    {
        dim3 g((NN + 127) / 128, 128 / 128);
        k_gemm2<128, 128, 8, 8><<<g, 256>>>(agg, x, Wl[0], Wr[0], bl[0], hA, NN, 128, 128);
    }
    // layer 1: 128 -> 64    (in: hA, out: hB)
    k_agg<128><<<aggBlocks, 256>>>(hA, agg);
    {
        dim3 g((NN + 127) / 128, 64 / 64);
        k_gemm2<128, 64, 8, 4><<<g, 256>>>(agg, hA, Wl[1], Wr[1], bl[1], hB, NN, 128, 64);
    }
    // layer 2: 64 -> 128    (in: hB, out: hA)
    k_agg<64><<<aggBlocks, 256>>>(hB, agg);
    {
        dim3 g((NN + 127) / 128, 128 / 128);
        k_gemm2<128, 128, 8, 8><<<g, 256>>>(agg, hB, Wl[2], Wr[2], bl[2], hA, NN, 64, 128);
    }
    // layer 3: 128 -> 256   (in: hA, out: hB)
    k_agg<128><<<aggBlocks, 256>>>(hA, agg);
    {
        dim3 g((NN + 127) / 128, 256 / 128);
        k_gemm2<128, 128, 8, 8><<<g, 256>>>(agg, hA, Wl[3], Wr[3], bl[3], hB, NN, 128, 256);
    }
    // layer 4: 256 -> 512   (in: hB, out: hA)
    k_agg<256><<<aggBlocks, 256>>>(hB, agg);
    {
        dim3 g((NN + 127) / 128, 512 / 128);
        k_gemm2<128, 128, 8, 8><<<g, 256>>>(agg, hB, Wl[4], Wr[4], bl[4], hA, NN, 256, 512);
    }
    // output: 512 -> 4 + softmax
    k_out<<<aggBlocks, 256>>>(hA, Wout, bout, out);
}

// round 11
// speedup vs baseline: 1.0117x; 1.0117x over previous
#include <cuda_runtime.h>
#include <cuda_bf16.h>
#include <mma.h>
#include <cstdint>
#include <math.h>

using namespace nvcuda;

#define NN 50000
#define EE 800000

// ---------------- scratch (static device globals; no allocation) ----------------
__device__ float g_hA[(size_t)NN * 512];
__device__ float g_hB[(size_t)NN * 512];
__device__ __nv_bfloat16 g_Ah[(size_t)NN * 256];
__device__ __nv_bfloat16 g_Al[(size_t)NN * 256];
__device__ __nv_bfloat16 g_H0h[(size_t)NN * 256];
__device__ __nv_bfloat16 g_H0l[(size_t)NN * 256];
__device__ __nv_bfloat16 g_H1h[(size_t)NN * 256];
__device__ __nv_bfloat16 g_H1l[(size_t)NN * 256];
#define WTOT 196608
__device__ __nv_bfloat16 g_WLh[WTOT];
__device__ __nv_bfloat16 g_WLl[WTOT];
__device__ __nv_bfloat16 g_WRh[WTOT];
__device__ __nv_bfloat16 g_WRl[WTOT];
__device__ int   g_deg[NN];
__device__ float g_deginv[NN];
__device__ int   g_rowptr[NN + 1];
__device__ int   g_cursor[NN];
__device__ int   g_col[EE];
__device__ int   g_aux[64];

// ---------------- CSR build ----------------
__global__ void k_zero_deg() {
    int i = blockIdx.x * blockDim.x + threadIdx.x;
    if (i < NN) g_deg[i] = 0;
}
__global__ void k_hist(const int* __restrict__ dst) {
    int e = blockIdx.x * blockDim.x + threadIdx.x;
    if (e < EE) atomicAdd(&g_deg[dst[e]], 1);
}
__global__ void k_scanA() {
    __shared__ int s[1024];
    int t = threadIdx.x;
    int i = blockIdx.x * 1024 + t;
    int v = (i < NN) ? g_deg[i] : 0;
    s[t] = v;
    __syncthreads();
    for (int off = 1; off < 1024; off <<= 1) {
        int x = (t >= off) ? s[t - off] : 0;
        __syncthreads();
        s[t] += x;
        __syncthreads();
    }
    if (i < NN) g_rowptr[i + 1] = s[t];
    if (t == 1023) g_aux[blockIdx.x] = s[t];
    if (i == 0) g_rowptr[0] = 0;
}
__global__ void k_scanB(int nb) {
    if (threadIdx.x == 0 && blockIdx.x == 0) {
        int run = 0;
        for (int b = 0; b < nb; b++) { int v = g_aux[b]; g_aux[b] = run; run += v; }
    }
}
__global__ void k_scanC() {
    int t = threadIdx.x;
    int i = blockIdx.x * 1024 + t;
    if (i < NN) g_rowptr[i + 1] += g_aux[blockIdx.x];
}
__global__ void k_prep() {
    int i = blockIdx.x * blockDim.x + threadIdx.x;
    if (i < NN) {
        g_cursor[i] = g_rowptr[i];
        g_deginv[i] = 1.0f / fmaxf((float)g_deg[i], 1.0f);
    }
}
__global__ void k_scatter(const int* __restrict__ src, const int* __restrict__ dst) {
    int e = blockIdx.x * blockDim.x + threadIdx.x;
    if (e < EE) {
        int d = dst[e];
        int pos = atomicAdd(&g_cursor[d], 1);
        g_col[pos] = src[e];
    }
}

// ---------------- mean aggregation: warp per node, 4-way unroll -> split-bf16 ----------------
template <int DIN>
__global__ void k_agg(const float* __restrict__ h, __nv_bfloat16* __restrict__ oh,
                      __nv_bfloat16* __restrict__ ol) {
    int warp = (blockIdx.x * blockDim.x + threadIdx.x) >> 5;
    int lane = threadIdx.x & 31;
    if (warp >= NN) return;
    constexpr int C = DIN / 32;
    float acc[C];
#pragma unroll
    for (int c = 0; c < C; c++) acc[c] = 0.0f;
    const int s = g_rowptr[warp];
    const int e = g_rowptr[warp + 1];
    int j = s;
    for (; j + 3 < e; j += 4) {
        int s0 = g_col[j];
        int s1 = g_col[j + 1];
        int s2 = g_col[j + 2];
        int s3 = g_col[j + 3];
        const float* r0 = h + (size_t)s0 * DIN;
        const float* r1 = h + (size_t)s1 * DIN;
        const float* r2 = h + (size_t)s2 * DIN;
        const float* r3 = h + (size_t)s3 * DIN;
        float v0[C], v1[C], v2[C], v3[C];
#pragma unroll
        for (int c = 0; c < C; c++) v0[c] = r0[lane + 32 * c];
#pragma unroll
        for (int c = 0; c < C; c++) v1[c] = r1[lane + 32 * c];
#pragma unroll
        for (int c = 0; c < C; c++) v2[c] = r2[lane + 32 * c];
#pragma unroll
        for (int c = 0; c < C; c++) v3[c] = r3[lane + 32 * c];
#pragma unroll
        for (int c = 0; c < C; c++) acc[c] += (v0[c] + v1[c]) + (v2[c] + v3[c]);
    }
    for (; j < e; j++) {
        const float* r0 = h + (size_t)g_col[j] * DIN;
#pragma unroll
        for (int c = 0; c < C; c++) acc[c] += r0[lane + 32 * c];
    }
    float di = g_deginv[warp];
#pragma unroll
    for (int c = 0; c < C; c++) {
        float v = acc[c] * di;
        __nv_bfloat16 bh = __float2bfloat16(v);
        __nv_bfloat16 bl = __float2bfloat16(v - __bfloat162float(bh));
        oh[(size_t)warp * DIN + lane + 32 * c] = bh;
        ol[(size_t)warp * DIN + lane + 32 * c] = bl;
    }
}

// ---------------- fp32 -> split bf16 conversion (for x and weights) ----------------
__global__ void k_conv(const float* __restrict__ src, __nv_bfloat16* __restrict__ hi,
                       __nv_bfloat16* __restrict__ lo, int n4) {
    int i = blockIdx.x * blockDim.x + threadIdx.x;
    if (i >= n4) return;
    float4 v = reinterpret_cast<const float4*>(src)[i];
    float f[4] = {v.x, v.y, v.z, v.w};
    __nv_bfloat16 h[4], l[4];
#pragma unroll
    for (int j = 0; j < 4; j++) {
        h[j] = __float2bfloat16(f[j]);
        l[j] = __float2bfloat16(f[j] - __bfloat162float(h[j]));
    }
    reinterpret_cast<__nv_bfloat162*>(hi)[2 * i + 0] = __nv_bfloat162(h[0], h[1]);
    reinterpret_cast<__nv_bfloat162*>(hi)[2 * i + 1] = __nv_bfloat162(h[2], h[3]);
    reinterpret_cast<__nv_bfloat162*>(lo)[2 * i + 0] = __nv_bfloat162(l[0], l[1]);
    reinterpret_cast<__nv_bfloat162*>(lo)[2 * i + 1] = __nv_bfloat162(l[2], l[3]);
}

// ---------------- wmma split-bf16 dual GEMM + bias + relu (portable HMMA path) ----------------
// C[128 x BN] = A1*W1^T + A2*W2^T (split hi/lo: hh + hl + lh), fp32 accum.
// 256 threads = 8 warps in 4x2; warp tile 32 x (BN/2). BK=64.
template <int BN>
__global__ __launch_bounds__(256, 1) void k_wgemm(
    const __nv_bfloat16* __restrict__ A1h, const __nv_bfloat16* __restrict__ A1l,
    const __nv_bfloat16* __restrict__ A2h, const __nv_bfloat16* __restrict__ A2l,
    const __nv_bfloat16* __restrict__ B1h, const __nv_bfloat16* __restrict__ B1l,
    const __nv_bfloat16* __restrict__ B2h, const __nv_bfloat16* __restrict__ B2l,
    const float* __restrict__ bias, float* __restrict__ C,
    __nv_bfloat16* __restrict__ Hnh, __nv_bfloat16* __restrict__ Hnl,
    int M, int K, int NO) {
    constexpr int BK = 64;
    constexpr int STR = BK + 8;            // bf16 stride (16B-aligned: 72*2=144)
    constexpr int WN = BN / 2;             // warp n-extent
    constexpr int NT = WN / 16;            // n fragment tiles per warp
    extern __shared__ char smem[];
    __nv_bfloat16* sAh = (__nv_bfloat16*)smem;
    __nv_bfloat16* sAl = sAh + 128 * STR;
    __nv_bfloat16* sBh = sAl + 128 * STR;
    __nv_bfloat16* sBl = sBh + BN * STR;
    float* stage = (float*)smem;           // reused after compute

    const int tid = threadIdx.x;
    const int wid = tid >> 5;
    const int lane = tid & 31;
    const int warpM = wid & 3;             // 0..3 -> m offset 32*warpM
    const int warpN = wid >> 2;            // 0..1 -> n offset WN*warpN
    const int m0 = blockIdx.x * 128;
    const int col0 = blockIdx.y * BN;

    wmma::fragment<wmma::accumulator, 16, 16, 16, float> acc[2][NT];
#pragma unroll
    for (int mt = 0; mt < 2; mt++)
#pragma unroll
        for (int nt = 0; nt < NT; nt++) wmma::fill_fragment(acc[mt][nt], 0.0f);

    for (int op = 0; op < 2; op++) {
        const __nv_bfloat16* Ah = op ? A2h : A1h;
        const __nv_bfloat16* Al = op ? A2l : A1l;
        const __nv_bfloat16* Bh = op ? B2h : B1h;
        const __nv_bfloat16* Bl = op ? B2l : B1l;
        for (int k0 = 0; k0 < K; k0 += BK) {
            // fill A tiles (128 x 64, hi+lo), 8 uint4 per row
            for (int idx = tid; idx < 128 * 8; idx += 256) {
                int r = idx >> 3, c8 = idx & 7;
                int gr = m0 + r;
                uint4 vh = make_uint4(0, 0, 0, 0), vl = make_uint4(0, 0, 0, 0);
                if (gr < M) {
                    vh = *reinterpret_cast<const uint4*>(Ah + (size_t)gr * K + k0 + c8 * 8);
                    vl = *reinterpret_cast<const uint4*>(Al + (size_t)gr * K + k0 + c8 * 8);
                }
                *reinterpret_cast<uint4*>(sAh + r * STR + c8 * 8) = vh;
                *reinterpret_cast<uint4*>(sAl + r * STR + c8 * 8) = vl;
            }
            // fill B tiles (BN x 64, hi+lo)
            for (int idx = tid; idx < BN * 8; idx += 256) {
                int r = idx >> 3, c8 = idx & 7;
                int gn = col0 + r;
                uint4 vh = *reinterpret_cast<const uint4*>(Bh + (size_t)gn * K + k0 + c8 * 8);
                uint4 vl = *reinterpret_cast<const uint4*>(Bl + (size_t)gn * K + k0 + c8 * 8);
                *reinterpret_cast<uint4*>(sBh + r * STR + c8 * 8) = vh;
                *reinterpret_cast<uint4*>(sBl + r * STR + c8 * 8) = vl;
            }
            __syncthreads();
#pragma unroll
            for (int ks = 0; ks < BK / 16; ks++) {
                wmma::fragment<wmma::matrix_a, 16, 16, 16, __nv_bfloat16, wmma::row_major> ah[2], al[2];
#pragma unroll
                for (int mt = 0; mt < 2; mt++) {
                    int ar = warpM * 32 + mt * 16;
                    wmma::load_matrix_sync(ah[mt], sAh + ar * STR + ks * 16, STR);
                    wmma::load_matrix_sync(al[mt], sAl + ar * STR + ks * 16, STR);
                }
#pragma unroll
                for (int nt = 0; nt < NT; nt++) {
                    int br = warpN * WN + nt * 16;
                    wmma::fragment<wmma::matrix_b, 16, 16, 16, __nv_bfloat16, wmma::col_major> bh, blo;
                    wmma::load_matrix_sync(bh, sBh + br * STR + ks * 16, STR);
                    wmma::load_matrix_sync(blo, sBl + br * STR + ks * 16, STR);
#pragma unroll
                    for (int mt = 0; mt < 2; mt++) {
                        wmma::mma_sync(acc[mt][nt], ah[mt], bh, acc[mt][nt]);
                        wmma::mma_sync(acc[mt][nt], ah[mt], blo, acc[mt][nt]);
                        wmma::mma_sync(acc[mt][nt], al[mt], bh, acc[mt][nt]);
                    }
                }
            }
            __syncthreads();
        }
    }

    // epilogue: stage per-warp 32 x WN tile in smem, then vectorized global writes
    float* wstage = stage + (size_t)wid * 32 * WN;
#pragma unroll
    for (int mt = 0; mt < 2; mt++)
#pragma unroll
        for (int nt = 0; nt < NT; nt++)
            wmma::store_matrix_sync(wstage + mt * 16 * WN + nt * 16, acc[mt][nt], WN, wmma::mem_row_major);
    __syncwarp();

    const int row = m0 + warpM * 32 + lane;
    const int cb = col0 + warpN * WN;
    if (row < M) {
        const float* srow = wstage + lane * WN;
        float* crow = C + (size_t)row * NO + cb;
        const float* brow = bias + cb;
        float v[WN];
#pragma unroll
        for (int j = 0; j < WN; j++) v[j] = fmaxf(srow[j] + brow[j], 0.0f);
#pragma unroll
        for (int j4 = 0; j4 < WN / 4; j4++)
            reinterpret_cast<float4*>(crow)[j4] =
                make_float4(v[4 * j4], v[4 * j4 + 1], v[4 * j4 + 2], v[4 * j4 + 3]);
        if (Hnh) {
            __nv_bfloat162* ph = reinterpret_cast<__nv_bfloat162*>(Hnh + (size_t)row * NO + cb);
            __nv_bfloat162* pl = reinterpret_cast<__nv_bfloat162*>(Hnl + (size_t)row * NO + cb);
#pragma unroll
            for (int j2 = 0; j2 < WN / 2; j2++) {
                float f0 = v[2 * j2], f1 = v[2 * j2 + 1];
                __nv_bfloat16 h0 = __float2bfloat16(f0);
                __nv_bfloat16 h1 = __float2bfloat16(f1);
                __nv_bfloat16 l0 = __float2bfloat16(f0 - __bfloat162float(h0));
                __nv_bfloat16 l1 = __float2bfloat16(f1 - __bfloat162float(h1));
                ph[j2] = __nv_bfloat162(h0, h1);
                pl[j2] = __nv_bfloat162(l0, l1);
            }
        }
    }
}

// ---------------- final linear (512 -> 4) + softmax, warp per node ----------------
__global__ void k_out(const float* __restrict__ h, const float* __restrict__ Wout,
                      const float* __restrict__ bout, float* __restrict__ out) {
    int warp = (blockIdx.x * blockDim.x + threadIdx.x) >> 5;
    int lane = threadIdx.x & 31;
    if (warp >= NN) return;
    const float* row = h + (size_t)warp * 512;
    float acc[4] = {0.f, 0.f, 0.f, 0.f};
    for (int j = lane; j < 512; j += 32) {
        float x = row[j];
#pragma unroll
        for (int o = 0; o < 4; o++) acc[o] += x * Wout[o * 512 + j];
    }
#pragma unroll
    for (int o = 0; o < 4; o++) {
#pragma unroll
        for (int off = 16; off; off >>= 1) acc[o] += __shfl_xor_sync(0xffffffffu, acc[o], off);
    }
    if (lane == 0) {
        float l[4];
#pragma unroll
        for (int o = 0; o < 4; o++) l[o] = acc[o] + bout[o];
        float m = fmaxf(fmaxf(l[0], l[1]), fmaxf(l[2], l[3]));
        float e[4], s = 0.f;
#pragma unroll
        for (int o = 0; o < 4; o++) { e[o] = expf(l[o] - m); s += e[o]; }
        float inv = 1.0f / s;
#pragma unroll
        for (int o = 0; o < 4; o++) out[(size_t)warp * 4 + o] = e[o] * inv;
    }
}

// ---------------- host side ----------------
extern "C" void kernel_launch(void* const* d_in, const int* in_sizes, int n_in,
                              void* d_out, int out_size) {
    const float* x = (const float*)d_in[0];
    const float* Wl[5];
    const float* bl[5];
    const float* Wr[5];
    for (int i = 0; i < 5; i++) {
        Wl[i] = (const float*)d_in[1 + 3 * i];
        bl[i] = (const float*)d_in[2 + 3 * i];
        Wr[i] = (const float*)d_in[3 + 3 * i];
    }
    const float* Wout = (const float*)d_in[16];
    const float* bout = (const float*)d_in[17];
    const int* edge = (const int*)d_in[18];
    const int* srcp = edge;
    const int* dstp = edge + EE;
    float* out = (float*)d_out;

    float *hA, *hB;
    __nv_bfloat16 *Ah, *Al, *H0h, *H0l, *H1h, *H1l, *WLh, *WLl, *WRh, *WRl;
    cudaGetSymbolAddress((void**)&hA, g_hA);
    cudaGetSymbolAddress((void**)&hB, g_hB);
    cudaGetSymbolAddress((void**)&Ah, g_Ah);
    cudaGetSymbolAddress((void**)&Al, g_Al);
    cudaGetSymbolAddress((void**)&H0h, g_H0h);
    cudaGetSymbolAddress((void**)&H0l, g_H0l);
    cudaGetSymbolAddress((void**)&H1h, g_H1h);
    cudaGetSymbolAddress((void**)&H1l, g_H1l);
    cudaGetSymbolAddress((void**)&WLh, g_WLh);
    cudaGetSymbolAddress((void**)&WLl, g_WLl);
    cudaGetSymbolAddress((void**)&WRh, g_WRh);
    cudaGetSymbolAddress((void**)&WRl, g_WRl);

    // smem: operands = (128 + BN) * 72 * 2 * 2 bytes; staging = 8*32*(BN/2)*4 (smaller)
    const int smem128 = (128 + 128) * 72 * 2 * 2;  // 73728
    const int smem64 = (128 + 64) * 72 * 2 * 2;    // 55296
    cudaFuncSetAttribute(k_wgemm<128>, cudaFuncAttributeMaxDynamicSharedMemorySize, smem128);
    cudaFuncSetAttribute(k_wgemm<64>, cudaFuncAttributeMaxDynamicSharedMemorySize, smem64);

    const int Ks[5] = {128, 128, 64, 128, 256};
    const int NOs[5] = {128, 64, 128, 256, 512};
    size_t woff[5];
    {
        size_t r = 0;
        for (int l = 0; l < 5; l++) { woff[l] = r; r += (size_t)NOs[l] * Ks[l]; }
    }

    // ---- weight + input conversion to split bf16 ----
    for (int l = 0; l < 5; l++) {
        int n4 = NOs[l] * Ks[l] / 4;
        k_conv<<<(n4 + 255) / 256, 256>>>(Wl[l], WLh + woff[l], WLl + woff[l], n4);
        k_conv<<<(n4 + 255) / 256, 256>>>(Wr[l], WRh + woff[l], WRl + woff[l], n4);
    }
    {
        int n4 = NN * 128 / 4;
        k_conv<<<(n4 + 255) / 256, 256>>>(x, H0h, H0l, n4);
    }

    // ---- CSR build ----
    const int nbScan = (NN + 1023) / 1024;
    k_zero_deg<<<(NN + 255) / 256, 256>>>();
    k_hist<<<(EE + 255) / 256, 256>>>(dstp);
    k_scanA<<<nbScan, 1024>>>();
    k_scanB<<<1, 32>>>(nbScan);
    k_scanC<<<nbScan, 1024>>>();
    k_prep<<<(NN + 255) / 256, 256>>>();
    k_scatter<<<(EE + 255) / 256, 256>>>(srcp, dstp);

    const int aggBlocks = (NN * 32 + 255) / 256;
    const int mTiles = (NN + 127) / 128;

    const float* hprev = x;                       // fp32 activations (for agg)
    __nv_bfloat16 *Hch = H0h, *Hcl = H0l;         // split-bf16 of hprev
    __nv_bfloat16 *Hnh = H1h, *Hnl = H1l;
    float* houts[5] = {hA, hB, hA, hB, hA};

    for (int l = 0; l < 5; l++) {
        int K = Ks[l], NO = NOs[l];
        if (K == 128) k_agg<128><<<aggBlocks, 256>>>(hprev, Ah, Al);
        else if (K == 64) k_agg<64><<<aggBlocks, 256>>>(hprev, Ah, Al);
        else k_agg<256><<<aggBlocks, 256>>>(hprev, Ah, Al);

        __nv_bfloat16* nh = (l < 4) ? Hnh : (__nv_bfloat16*)nullptr;
        __nv_bfloat16* nl = (l < 4) ? Hnl : (__nv_bfloat16*)nullptr;
        if (NO >= 128) {
            dim3 g(mTiles, NO / 128);
            k_wgemm<128><<<g, 256, smem128>>>(Ah, Al, Hch, Hcl,
                                              WLh + woff[l], WLl + woff[l],
                                              WRh + woff[l], WRl + woff[l],
                                              bl[l], houts[l], nh, nl, NN, K, NO);
        } else {
            dim3 g(mTiles, 1);
            k_wgemm<64><<<g, 256, smem64>>>(Ah, Al, Hch, Hcl,
                                            WLh + woff[l], WLl + woff[l],
                                            WRh + woff[l], WRl + woff[l],
                                            bl[l], houts[l], nh, nl, NN, K, NO);
        }
        hprev = houts[l];
        __nv_bfloat16* th = Hch; Hch = Hnh; Hnh = th;
        __nv_bfloat16* tl = Hcl; Hcl = Hnl; Hnl = tl;
    }

    k_out<<<aggBlocks, 256>>>(hprev, Wout, bout, out);
}